// round 7
// baseline (speedup 1.0000x reference)
#include <cuda_runtime.h>
#include <cstdint>
#include <cstddef>

// ---------------------------------------------------------------------------
// NonLocalBlock: B=16, C=64, H=W=64, C1=8, C2=32
// out = gamma * conv1x1(attn_out, w_last, b_last) + x
// Attn: 512 thr/CTA, channel-split (2 queries x 16 V-channels per thread)
// -> 16 warps/SM at ~100 regs/thread, no spills, K+V resident in smem.
// ---------------------------------------------------------------------------

#define DINL __device__ __forceinline__

DINL unsigned long long pk2(float lo, float hi) {
    unsigned long long r;
    asm("mov.b64 %0, {%1, %2};" : "=l"(r) : "f"(lo), "f"(hi));
    return r;
}
DINL void upk2(unsigned long long v, float& lo, float& hi) {
    asm("mov.b64 {%0, %1}, %2;" : "=f"(lo), "=f"(hi) : "l"(v));
}
DINL unsigned long long fma2(unsigned long long a, unsigned long long b, unsigned long long c) {
    unsigned long long d;
    asm("fma.rn.f32x2 %0, %1, %2, %3;" : "=l"(d) : "l"(a), "l"(b), "l"(c));
    return d;
}
DINL unsigned long long mul2(unsigned long long a, unsigned long long b) {
    unsigned long long d;
    asm("mul.rn.f32x2 %0, %1, %2;" : "=l"(d) : "l"(a), "l"(b));
    return d;
}
DINL float ex2(float x) {
    float r;
    asm("ex2.approx.f32 %0, %1;" : "=f"(r) : "f"(x));
    return r;
}

// scratch (no allocation allowed -> __device__ globals)
__device__ float g_delta[16 * 4096 * 8];   // [b][n][8]
__device__ float g_phiP [16 * 8 * 1024];   // [b][c1][1024]
__device__ float g_gP   [16 * 1024 * 32];  // [b][m][32]

// ---------------------------------------------------------------------------
// Kernel 1: fused 3x conv1x1 (48 out ch) + 2x2 maxpool for phi/g.
// One thread per 2x1 pixel column; thread pairs merge pooling via shfl_xor(1).
// grid (8,16), 256 threads. (~5us wall with warm L2.)
// ---------------------------------------------------------------------------
__global__ __launch_bounds__(256, 1) void conv_pool_kernel(
    const float* __restrict__ x,
    const float* __restrict__ w_delta, const float* __restrict__ b_delta,
    const float* __restrict__ w_phi,   const float* __restrict__ b_phi,
    const float* __restrict__ w_g,     const float* __restrict__ b_g)
{
    __shared__ ulonglong2 ws[64][12];
    __shared__ float bias[48];
    const int tid = threadIdx.x;

    for (int i = tid; i < 3072; i += 256) {
        int c = i / 48, o = i - c * 48;
        float w;
        if (o < 8)       w = w_delta[o * 64 + c];
        else if (o < 16) w = w_phi[(o - 8) * 64 + c];
        else             w = w_g[(o - 16) * 64 + c];
        ((float*)&ws[c][0])[o] = w;
    }
    if (tid < 48)
        bias[tid] = (tid < 8) ? b_delta[tid] : (tid < 16) ? b_phi[tid - 8] : b_g[tid - 16];
    __syncthreads();

    const int b   = blockIdx.y;
    const int t   = blockIdx.x * 256 + tid;
    const int q   = t >> 1;
    const int col = t & 1;
    const int qy  = q >> 5, qx = q & 31;
    const int xcol = 2 * qx + col;
    const int row0 = 2 * qy;

    const float* xp = x + (size_t)b * 262144 + row0 * 64 + xcol;

    unsigned long long a0[24], a1[24];
#pragma unroll
    for (int k = 0; k < 24; k++) { a0[k] = 0ull; a1[k] = 0ull; }

#pragma unroll 4
    for (int c = 0; c < 64; c++) {
        float xv0 = xp[c * 4096];
        float xv1 = xp[c * 4096 + 64];
        unsigned long long x0 = pk2(xv0, xv0);
        unsigned long long x1 = pk2(xv1, xv1);
#pragma unroll
        for (int k = 0; k < 12; k++) {
            ulonglong2 w = ws[c][k];
            a0[2*k]   = fma2(w.x, x0, a0[2*k]);
            a0[2*k+1] = fma2(w.y, x0, a0[2*k+1]);
            a1[2*k]   = fma2(w.x, x1, a1[2*k]);
            a1[2*k+1] = fma2(w.y, x1, a1[2*k+1]);
        }
    }

    float f0[48], f1[48];
#pragma unroll
    for (int k = 0; k < 24; k++) {
        upk2(a0[k], f0[2*k], f0[2*k+1]);
        upk2(a1[k], f1[2*k], f1[2*k+1]);
    }

    float* dp0 = g_delta + ((size_t)(b * 4096 + row0 * 64 + xcol)) * 8;
#pragma unroll
    for (int j = 0; j < 8; j++) {
        dp0[j]          = f0[j] + bias[j];
        dp0[64 * 8 + j] = f1[j] + bias[j];
    }

    float pm[40];
#pragma unroll
    for (int j = 0; j < 40; j++) {
        float v = fmaxf(f0[8 + j], f1[8 + j]);
        pm[j] = fmaxf(v, __shfl_xor_sync(0xffffffffu, v, 1));
    }
    float* gp = g_gP + ((size_t)(b * 1024 + q)) * 32;
    if (col == 0) {
#pragma unroll
        for (int j = 0; j < 8; j++)
            g_phiP[(b * 8 + j) * 1024 + q] = pm[j] + bias[8 + j];
#pragma unroll
        for (int j = 0; j < 16; j++)
            gp[j] = pm[8 + j] + bias[16 + j];
    } else {
#pragma unroll
        for (int j = 16; j < 32; j++)
            gp[j] = pm[8 + j] + bias[16 + j];
    }
}

// ---------------------------------------------------------------------------
// Kernel 2: fused attention + final conv + residual.
// grid (8,16): 512 queries/CTA. 512 threads: qslot = tid&255 -> queries
// (qslot, qslot+256); chalf = tid>>8 -> V channels [chalf*16, chalf*16+16).
// QK scores duplicated across chalf partners (cheap) so no sync in main loop.
// Key loop blocked by 8 (phase-split) for ILP. Single-pass no-max softmax.
// Epilogue: redistribute acc via smem (over Vsm), fused conv+residual.
// ---------------------------------------------------------------------------
__global__ __launch_bounds__(512, 1) void attn_kernel(
    const float* __restrict__ x,
    const float* __restrict__ w_last, const float* __restrict__ b_last,
    const float* __restrict__ gamma,  float* __restrict__ out)
{
    extern __shared__ float sm[];
    float* Vsm = sm;              // 1024*32 = 32768 floats (128 KB)
    float* Ksm = sm + 32768;      // 1024*8  =  8192 floats ( 32 KB)
    float* wl  = sm + 40960;      // 64*32   =  2048 floats (  8 KB)
    float* bl  = sm + 43008;      // 64

    const int tid   = threadIdx.x;
    const int b     = blockIdx.y;
    const int qslot = tid & 255;
    const int chalf = tid >> 8;        // 0 or 1, uniform per warp

    {   // V: [1024][32] straight copy
        const float4* src = (const float4*)(g_gP + (size_t)b * 32768);
        float4* dst = (float4*)Vsm;
        for (int i = tid; i < 8192; i += 512) dst[i] = src[i];
    }
    // K gather (reference batch-mix): K[b][j][m] = phiP[(b*8+j)%16][(b*8+j)/16][m]
#pragma unroll
    for (int j = 0; j < 8; j++) {
        int idx = b * 8 + j;
        const float* src = g_phiP + (size_t)((idx & 15) * 8 + (idx >> 4)) * 1024;
        for (int m = tid; m < 1024; m += 512) Ksm[m * 8 + j] = src[m];
    }
    for (int i = tid; i < 2048; i += 512) wl[i] = w_last[i];
    if (tid < 64) bl[tid] = b_last[tid];
    __syncthreads();

    const int q0 = blockIdx.x * 512 + qslot;
    const int q1 = q0 + 256;
    const ulonglong2* dq0 = (const ulonglong2*)(g_delta + ((size_t)b * 4096 + q0) * 8);
    const ulonglong2* dq1 = (const ulonglong2*)(g_delta + ((size_t)b * 4096 + q1) * 8);
    const unsigned long long L2E = pk2(1.4426950408889634f, 1.4426950408889634f);
    ulonglong2 qa, qb, qc, qd;
    { ulonglong2 r0 = dq0[0], r1 = dq0[1], r2 = dq1[0], r3 = dq1[1];
      qa.x = mul2(r0.x, L2E); qa.y = mul2(r0.y, L2E);
      qb.x = mul2(r1.x, L2E); qb.y = mul2(r1.y, L2E);
      qc.x = mul2(r2.x, L2E); qc.y = mul2(r2.y, L2E);
      qd.x = mul2(r3.x, L2E); qd.y = mul2(r3.y, L2E); }

    unsigned long long acc0[8], acc1[8];   // 2 queries x 16 channels as f32x2
#pragma unroll
    for (int k = 0; k < 8; k++) { acc0[k] = 0ull; acc1[k] = 0ull; }
    float l0 = 0.f, l1 = 0.f;

    const ulonglong2* K2 = (const ulonglong2*)Ksm;
    const ulonglong2* V2 = (const ulonglong2*)Vsm + chalf * 4;  // channel-half base

    for (int mb = 0; mb < 1024; mb += 8) {
        const ulonglong2* Kp = K2 + 2 * mb;
        const ulonglong2* Vp = V2 + 8 * mb;

        float e0[8], e1[8];
        // Phase A: 8 independent QK -> ex2 chains (duplicated across chalf)
#pragma unroll
        for (int u = 0; u < 8; u++) {
            ulonglong2 kA = Kp[2 * u], kB = Kp[2 * u + 1];      // broadcast LDS.128
            unsigned long long p0 = mul2(qa.x, kA.x);
            p0 = fma2(qa.y, kA.y, p0);
            p0 = fma2(qb.x, kB.x, p0);
            p0 = fma2(qb.y, kB.y, p0);
            unsigned long long p1 = mul2(qc.x, kA.x);
            p1 = fma2(qc.y, kA.y, p1);
            p1 = fma2(qd.x, kB.x, p1);
            p1 = fma2(qd.y, kB.y, p1);
            float s0a, s0b, s1a, s1b;
            upk2(p0, s0a, s0b);
            upk2(p1, s1a, s1b);
            e0[u] = ex2(s0a + s0b);
            e1[u] = ex2(s1a + s1b);
        }
        // Phase B: 8 independent PV rank-1 updates on this thread's 16 channels
#pragma unroll
        for (int u = 0; u < 8; u++) {
            unsigned long long e0p = pk2(e0[u], e0[u]);
            unsigned long long e1p = pk2(e1[u], e1[u]);
            l0 += e0[u];
            l1 += e1[u];
            const ulonglong2* v = Vp + 8 * u;                   // broadcast LDS.128 x4
#pragma unroll
            for (int t = 0; t < 4; t++) {
                ulonglong2 vv = v[t];
                acc0[2*t]   = fma2(e0p, vv.x, acc0[2*t]);
                acc0[2*t+1] = fma2(e0p, vv.y, acc0[2*t+1]);
                acc1[2*t]   = fma2(e1p, vv.x, acc1[2*t]);
                acc1[2*t+1] = fma2(e1p, vv.y, acc1[2*t+1]);
            }
        }
    }

    // ---- redistribute acc to smem (over Vsm; rows padded to 34 floats) ----
    __syncthreads();   // everyone done reading Vsm
    float* accS = sm;               // 512 rows x 34 floats = 17408 floats (68KB)
    float* lS   = sm + 17408;       // 512 floats
    {
        unsigned long long* r0 = (unsigned long long*)(accS + qslot * 34 + chalf * 16);
        unsigned long long* r1 = (unsigned long long*)(accS + (qslot + 256) * 34 + chalf * 16);
#pragma unroll
        for (int j = 0; j < 8; j++) { r0[j] = acc0[j]; r1[j] = acc1[j]; }
        if (chalf == 0) { lS[qslot] = l0; lS[qslot + 256] = l1; }
    }
    __syncthreads();

    // ---- fused epilogue: one query per thread ----
    const int qg = blockIdx.x * 512 + tid;    // row tid of accS == query qg
    unsigned long long au[16];
    {
        const unsigned long long* rr = (const unsigned long long*)(accS + tid * 34);
#pragma unroll
        for (int k = 0; k < 16; k++) au[k] = rr[k];
    }
    const float gm  = gamma[0];
    const float gi  = __fdividef(gm, lS[tid]);
    const float* xb = x   + (size_t)b * 262144;
    float*       ob = out + (size_t)b * 262144;
    const ulonglong2* wl2 = (const ulonglong2*)wl;

    for (int c = 0; c < 64; c++) {
        const ulonglong2* wr = wl2 + c * 8;
        ulonglong2 w0 = wr[0];
        unsigned long long s0 = mul2(au[0], w0.x);
        s0 = fma2(au[1], w0.y, s0);
#pragma unroll
        for (int t = 1; t < 8; t++) {
            ulonglong2 w = wr[t];
            s0 = fma2(au[2*t],   w.x, s0);
            s0 = fma2(au[2*t+1], w.y, s0);
        }
        float ra, rb;
        upk2(s0, ra, rb);
        ob[c * 4096 + qg] = fmaf(gi, ra + rb, fmaf(gm, bl[c], xb[c * 4096 + qg]));
    }
}

// ---------------------------------------------------------------------------
extern "C" void kernel_launch(void* const* d_in, const int* in_sizes, int n_in,
                              void* d_out, int out_size)
{
    const float* x  = (const float*)d_in[0];
    const float* wd = (const float*)d_in[1];
    const float* bd = (const float*)d_in[2];
    const float* wp = (const float*)d_in[3];
    const float* bp = (const float*)d_in[4];
    const float* wg = (const float*)d_in[5];
    const float* bg = (const float*)d_in[6];
    const float* wl = (const float*)d_in[7];
    const float* bl = (const float*)d_in[8];
    const float* gm = (const float*)d_in[9];

    conv_pool_kernel<<<dim3(8, 16), 256>>>(x, wd, bd, wp, bp, wg, bg);

    const int shm = (32768 + 8192 + 2048 + 64) * 4;  // 172288 B
    cudaFuncSetAttribute(attn_kernel, cudaFuncAttributeMaxDynamicSharedMemorySize, shm);
    attn_kernel<<<dim3(8, 16), 512, shm>>>(x, wl, bl, gm, (float*)d_out);
}

// round 9
// speedup vs baseline: 1.6840x; 1.6840x over previous
#include <cuda_runtime.h>
#include <cstdint>
#include <cstddef>

// ---------------------------------------------------------------------------
// NonLocalBlock: B=16, C=64, H=W=64, C1=8, C2=32
// out = gamma * conv1x1(attn_out, w_last, b_last) + x
// Attention: scalar QK+exp -> P smem tile -> mma.sync tf32 PV (HMMA),
// O accumulated in register C-frags; fused conv+residual epilogue.
// ---------------------------------------------------------------------------

#define DINL __device__ __forceinline__

DINL unsigned long long pk2(float lo, float hi) {
    unsigned long long r;
    asm("mov.b64 %0, {%1, %2};" : "=l"(r) : "f"(lo), "f"(hi));
    return r;
}
DINL void upk2(unsigned long long v, float& lo, float& hi) {
    asm("mov.b64 {%0, %1}, %2;" : "=f"(lo), "=f"(hi) : "l"(v));
}
DINL unsigned long long fma2(unsigned long long a, unsigned long long b, unsigned long long c) {
    unsigned long long d;
    asm("fma.rn.f32x2 %0, %1, %2, %3;" : "=l"(d) : "l"(a), "l"(b), "l"(c));
    return d;
}
DINL unsigned long long mul2(unsigned long long a, unsigned long long b) {
    unsigned long long d;
    asm("mul.rn.f32x2 %0, %1, %2;" : "=l"(d) : "l"(a), "l"(b));
    return d;
}
DINL float ex2(float x) {
    float r;
    asm("ex2.approx.f32 %0, %1;" : "=f"(r) : "f"(x));
    return r;
}
DINL uint32_t f2tf32(float v) {
    uint32_t u;
    asm("cvt.rna.tf32.f32 %0, %1;" : "=r"(u) : "f"(v));
    return u;
}

// m16n8k8 tf32 mma: C(f32) += A(tf32) * B(tf32)
#define MMA_TF32(c, a0, a1, a2, a3, b0, b1)                                   \
    asm volatile(                                                             \
        "mma.sync.aligned.m16n8k8.row.col.f32.tf32.tf32.f32 "                 \
        "{%0,%1,%2,%3}, {%4,%5,%6,%7}, {%8,%9}, {%0,%1,%2,%3};"               \
        : "+f"((c)[0]), "+f"((c)[1]), "+f"((c)[2]), "+f"((c)[3])              \
        : "r"(a0), "r"(a1), "r"(a2), "r"(a3), "r"(b0), "r"(b1))

// scratch (no allocation allowed -> __device__ globals)
__device__ float g_delta[16 * 4096 * 8];   // [b][n][8]
__device__ float g_phiP [16 * 8 * 1024];   // [b][c1][1024]
__device__ float g_gP   [16 * 1024 * 32];  // [b][m][32]

// ---------------------------------------------------------------------------
// Kernel 1: fused 3x conv1x1 (48 out ch) + 2x2 maxpool for phi/g. (proven)
// ---------------------------------------------------------------------------
__global__ __launch_bounds__(256, 1) void conv_pool_kernel(
    const float* __restrict__ x,
    const float* __restrict__ w_delta, const float* __restrict__ b_delta,
    const float* __restrict__ w_phi,   const float* __restrict__ b_phi,
    const float* __restrict__ w_g,     const float* __restrict__ b_g)
{
    __shared__ ulonglong2 ws[64][12];
    __shared__ float bias[48];
    const int tid = threadIdx.x;

    for (int i = tid; i < 3072; i += 256) {
        int c = i / 48, o = i - c * 48;
        float w;
        if (o < 8)       w = w_delta[o * 64 + c];
        else if (o < 16) w = w_phi[(o - 8) * 64 + c];
        else             w = w_g[(o - 16) * 64 + c];
        ((float*)&ws[c][0])[o] = w;
    }
    if (tid < 48)
        bias[tid] = (tid < 8) ? b_delta[tid] : (tid < 16) ? b_phi[tid - 8] : b_g[tid - 16];
    __syncthreads();

    const int b   = blockIdx.y;
    const int t   = blockIdx.x * 256 + tid;
    const int q   = t >> 1;
    const int col = t & 1;
    const int qy  = q >> 5, qx = q & 31;
    const int xcol = 2 * qx + col;
    const int row0 = 2 * qy;

    const float* xp = x + (size_t)b * 262144 + row0 * 64 + xcol;

    unsigned long long a0[24], a1[24];
#pragma unroll
    for (int k = 0; k < 24; k++) { a0[k] = 0ull; a1[k] = 0ull; }

#pragma unroll 4
    for (int c = 0; c < 64; c++) {
        float xv0 = xp[c * 4096];
        float xv1 = xp[c * 4096 + 64];
        unsigned long long x0 = pk2(xv0, xv0);
        unsigned long long x1 = pk2(xv1, xv1);
#pragma unroll
        for (int k = 0; k < 12; k++) {
            ulonglong2 w = ws[c][k];
            a0[2*k]   = fma2(w.x, x0, a0[2*k]);
            a0[2*k+1] = fma2(w.y, x0, a0[2*k+1]);
            a1[2*k]   = fma2(w.x, x1, a1[2*k]);
            a1[2*k+1] = fma2(w.y, x1, a1[2*k+1]);
        }
    }

    float f0[48], f1[48];
#pragma unroll
    for (int k = 0; k < 24; k++) {
        upk2(a0[k], f0[2*k], f0[2*k+1]);
        upk2(a1[k], f1[2*k], f1[2*k+1]);
    }

    float* dp0 = g_delta + ((size_t)(b * 4096 + row0 * 64 + xcol)) * 8;
#pragma unroll
    for (int j = 0; j < 8; j++) {
        dp0[j]          = f0[j] + bias[j];
        dp0[64 * 8 + j] = f1[j] + bias[j];
    }

    float pm[40];
#pragma unroll
    for (int j = 0; j < 40; j++) {
        float v = fmaxf(f0[8 + j], f1[8 + j]);
        pm[j] = fmaxf(v, __shfl_xor_sync(0xffffffffu, v, 1));
    }
    float* gp = g_gP + ((size_t)(b * 1024 + q)) * 32;
    if (col == 0) {
#pragma unroll
        for (int j = 0; j < 8; j++)
            g_phiP[(b * 8 + j) * 1024 + q] = pm[j] + bias[8 + j];
#pragma unroll
        for (int j = 0; j < 16; j++)
            gp[j] = pm[8 + j] + bias[16 + j];
    } else {
#pragma unroll
        for (int j = 16; j < 32; j++)
            gp[j] = pm[8 + j] + bias[16 + j];
    }
}

// ---------------------------------------------------------------------------
// Kernel 2: attention (scalar QK+exp, tf32 mma PV) + fused conv + residual.
// grid (8,16): 512 queries/CTA, 256 threads (8 warps).
// smem (floats):
//   Vsm : [32 c][1032]          @ 0      (33024)   tf32 bits of V, ones-free
//   Ksm : [1024 m][8]           @ 33024  ( 8192)   K * log2e  (R5 layout)
//   Psm : [16 k][520 q-pitch]   @ 41216  ( 8320)   exp(scores), per chunk
//   wls : w_last [64][32]       @ 49536  ( 2048)
//   bls : b_last                @ 51584  (   64)
// total 51648 floats = 206592 B. Osm reuses Vsm region in epilogue (512x33).
// ---------------------------------------------------------------------------
static constexpr int SM_FLOATS = 51648;

__global__ __launch_bounds__(256, 1) void attn_kernel(
    const float* __restrict__ x,
    const float* __restrict__ w_last, const float* __restrict__ b_last,
    const float* __restrict__ gamma,  float* __restrict__ out)
{
    extern __shared__ float sm[];
    float*    Vsm = sm;                 // as uint bits (tf32)
    float*    Ksm = sm + 33024;
    float*    Psm = sm + 41216;
    float*    wls = sm + 49536;
    float*    bls = sm + 51584;
    uint32_t* Vu  = (uint32_t*)Vsm;

    const int tid  = threadIdx.x;
    const int wid  = tid >> 5;
    const int lane = tid & 31;
    const int g    = lane >> 2;         // 0..7
    const int t    = lane & 3;          // 0..3
    const int b    = blockIdx.y;

    // V fill (transposed, tf32-rounded): Vu[c*1032 + m] = tf32(g_gP[b][m][c])
    for (int m = tid; m < 1024; m += 256) {
        const float4* gv = (const float4*)(g_gP + ((size_t)(b * 1024 + m)) * 32);
        float4 v4[8];
#pragma unroll
        for (int k = 0; k < 8; k++) v4[k] = gv[k];
        const float* vf = (const float*)v4;
#pragma unroll
        for (int c = 0; c < 32; c++) Vu[c * 1032 + m] = f2tf32(vf[c]);
    }
    // K fill (R5 layout [m][8], log2e folded), with reference batch-mix gather
    {
        const float L2E = 1.4426950408889634f;
#pragma unroll
        for (int j = 0; j < 8; j++) {
            int idx = b * 8 + j;
            const float* src = g_phiP + (size_t)((idx & 15) * 8 + (idx >> 4)) * 1024;
            for (int m = tid; m < 1024; m += 256) Ksm[m * 8 + j] = L2E * src[m];
        }
    }
    for (int i = tid; i < 2048; i += 256) wls[i] = w_last[i];
    if (tid < 64) bls[tid] = b_last[tid];
    __syncthreads();

    // q registers for this thread's 2 queries (lq0 = tid, lq1 = tid+256)
    const int lq0 = tid, lq1 = tid + 256;
    const ulonglong2* dq0 =
        (const ulonglong2*)(g_delta + ((size_t)b * 4096 + blockIdx.x * 512 + lq0) * 8);
    const ulonglong2* dq1 =
        (const ulonglong2*)(g_delta + ((size_t)b * 4096 + blockIdx.x * 512 + lq1) * 8);
    ulonglong2 qa = dq0[0], qb = dq0[1];
    ulonglong2 qc = dq1[0], qd = dq1[1];

    float l0 = 0.f, l1 = 0.f;
    float acc[4][16];                   // [i: q-tile wid*4+i][nt*4 + cfrag]
#pragma unroll
    for (int i = 0; i < 4; i++)
#pragma unroll
        for (int k = 0; k < 16; k++) acc[i][k] = 0.f;

    for (int ci = 0; ci < 64; ci++) {
        const int m0 = ci << 4;

        // ---- Phase A: scalar QK + exp -> Psm[k][q] (2 sub-blocks of 8) ----
#pragma unroll
        for (int sub = 0; sub < 2; sub++) {
            const ulonglong2* Kp = (const ulonglong2*)(Ksm + (m0 + sub * 8) * 8);
            float e0[8], e1[8];
#pragma unroll
            for (int u = 0; u < 8; u++) {
                ulonglong2 kA = Kp[2 * u], kB = Kp[2 * u + 1];  // broadcast LDS.128
                unsigned long long p0 = mul2(qa.x, kA.x);
                p0 = fma2(qa.y, kA.y, p0);
                p0 = fma2(qb.x, kB.x, p0);
                p0 = fma2(qb.y, kB.y, p0);
                unsigned long long p1 = mul2(qc.x, kA.x);
                p1 = fma2(qc.y, kA.y, p1);
                p1 = fma2(qd.x, kB.x, p1);
                p1 = fma2(qd.y, kB.y, p1);
                float s0a, s0b, s1a, s1b;
                upk2(p0, s0a, s0b);
                upk2(p1, s1a, s1b);
                e0[u] = ex2(s0a + s0b);
                e1[u] = ex2(s1a + s1b);
            }
#pragma unroll
            for (int u = 0; u < 8; u++) {
                l0 += e0[u];
                l1 += e1[u];
                float* pr = Psm + (sub * 8 + u) * 520;
                pr[lq0] = e0[u];        // conflict-free (consecutive lanes)
                pr[lq1] = e1[u];
            }
        }
        __syncthreads();

        // ---- Phase B: PV via tf32 mma; warp wid owns q-tiles wid*4+i ----
#pragma unroll
        for (int ks = 0; ks < 2; ks++) {
            const int kb = ks * 8;
            // B-frags: V[k][n] col-major; b0=(k=t,n=g), b1=(k=t+4,n=g)
            uint32_t bf[4][2];
#pragma unroll
            for (int nt = 0; nt < 4; nt++) {
                bf[nt][0] = Vu[(nt * 8 + g) * 1032 + m0 + kb + t];
                bf[nt][1] = Vu[(nt * 8 + g) * 1032 + m0 + kb + t + 4];
            }
#pragma unroll
            for (int i = 0; i < 4; i++) {
                const int qbse = (wid * 4 + i) * 16;
                // A-frags from Psm[k][q]: a0=(q=g,k=t) a1=(q=g+8,k=t)
                //                          a2=(q=g,k=t+4) a3=(q=g+8,k=t+4)
                const float* r0 = Psm + (kb + t) * 520 + qbse;
                const float* r1 = Psm + (kb + t + 4) * 520 + qbse;
                uint32_t a0 = __float_as_uint(r0[g]);
                uint32_t a1 = __float_as_uint(r0[g + 8]);
                uint32_t a2 = __float_as_uint(r1[g]);
                uint32_t a3 = __float_as_uint(r1[g + 8]);
                MMA_TF32(acc[i] + 0,  a0, a1, a2, a3, bf[0][0], bf[0][1]);
                MMA_TF32(acc[i] + 4,  a0, a1, a2, a3, bf[1][0], bf[1][1]);
                MMA_TF32(acc[i] + 8,  a0, a1, a2, a3, bf[2][0], bf[2][1]);
                MMA_TF32(acc[i] + 12, a0, a1, a2, a3, bf[3][0], bf[3][1]);
            }
        }
        __syncthreads();   // before next chunk's Phase A overwrites Psm
    }

    // ---- scatter O c-frags to smem (over Vsm region): Osm[q][33] ----
    float* Osm = sm;
#pragma unroll
    for (int i = 0; i < 4; i++) {
        const int qbse = (wid * 4 + i) * 16;
#pragma unroll
        for (int nt = 0; nt < 4; nt++) {
            const int cb = nt * 8 + 2 * t;
            Osm[(qbse + g)     * 33 + cb]     = acc[i][nt * 4 + 0];
            Osm[(qbse + g)     * 33 + cb + 1] = acc[i][nt * 4 + 1];
            Osm[(qbse + g + 8) * 33 + cb]     = acc[i][nt * 4 + 2];
            Osm[(qbse + g + 8) * 33 + cb + 1] = acc[i][nt * 4 + 3];
        }
    }
    __syncthreads();

    // ---- fused epilogue (R5-proven math): 2 queries per thread ----
    unsigned long long au0[16], au1[16];
    {
        const float* o0 = Osm + lq0 * 33;
        const float* o1 = Osm + lq1 * 33;
#pragma unroll
        for (int k = 0; k < 16; k++) {
            au0[k] = pk2(o0[2 * k], o0[2 * k + 1]);
            au1[k] = pk2(o1[2 * k], o1[2 * k + 1]);
        }
    }
    const int qg0 = blockIdx.x * 512 + lq0;
    const int qg1 = qg0 + 256;
    const float gm  = gamma[0];
    const float gi0 = __fdividef(gm, l0);
    const float gi1 = __fdividef(gm, l1);
    const float* xb = x   + (size_t)b * 262144;
    float*       ob = out + (size_t)b * 262144;
    const ulonglong2* wl2 = (const ulonglong2*)wls;

    for (int c = 0; c < 64; c++) {
        const ulonglong2* wr = wl2 + c * 8;
        ulonglong2 w0 = wr[0];
        unsigned long long s0 = mul2(au0[0], w0.x);
        unsigned long long s1 = mul2(au1[0], w0.x);
        s0 = fma2(au0[1], w0.y, s0);
        s1 = fma2(au1[1], w0.y, s1);
#pragma unroll
        for (int k = 1; k < 8; k++) {
            ulonglong2 w = wr[k];
            s0 = fma2(au0[2*k],   w.x, s0);
            s1 = fma2(au1[2*k],   w.x, s1);
            s0 = fma2(au0[2*k+1], w.y, s0);
            s1 = fma2(au1[2*k+1], w.y, s1);
        }
        float r0a, r0b, r1a, r1b;
        upk2(s0, r0a, r0b);
        upk2(s1, r1a, r1b);
        float base = gm * bls[c];
        ob[c * 4096 + qg0] = fmaf(gi0, r0a + r0b, base + xb[c * 4096 + qg0]);
        ob[c * 4096 + qg1] = fmaf(gi1, r1a + r1b, base + xb[c * 4096 + qg1]);
    }
}

// ---------------------------------------------------------------------------
extern "C" void kernel_launch(void* const* d_in, const int* in_sizes, int n_in,
                              void* d_out, int out_size)
{
    const float* x  = (const float*)d_in[0];
    const float* wd = (const float*)d_in[1];
    const float* bd = (const float*)d_in[2];
    const float* wp = (const float*)d_in[3];
    const float* bp = (const float*)d_in[4];
    const float* wg = (const float*)d_in[5];
    const float* bg = (const float*)d_in[6];
    const float* wl = (const float*)d_in[7];
    const float* bl = (const float*)d_in[8];
    const float* gm = (const float*)d_in[9];

    conv_pool_kernel<<<dim3(8, 16), 256>>>(x, wd, bd, wp, bp, wg, bg);

    const int shm = SM_FLOATS * 4;   // 206592 B
    cudaFuncSetAttribute(attn_kernel, cudaFuncAttributeMaxDynamicSharedMemorySize, shm);
    attn_kernel<<<dim3(8, 16), 256, shm>>>(x, wl, bl, gm, (float*)d_out);
}

// round 12
// speedup vs baseline: 2.3239x; 1.3800x over previous
#include <cuda_runtime.h>
#include <cstdint>
#include <cstddef>

// ---------------------------------------------------------------------------
// NonLocalBlock: B=16, C=64, H=W=64, C1=8, C2=32
// out = gamma * conv1x1(attn_out, w_last, b_last) + x
// Attention v3: QK AND PV on tensor pipe (mma.sync tf32), exp in registers,
// per-warp P staging (no CTA barriers in main loop), fused conv epilogue.
// ---------------------------------------------------------------------------

#define DINL __device__ __forceinline__

DINL unsigned long long pk2(float lo, float hi) {
    unsigned long long r;
    asm("mov.b64 %0, {%1, %2};" : "=l"(r) : "f"(lo), "f"(hi));
    return r;
}
DINL void upk2(unsigned long long v, float& lo, float& hi) {
    asm("mov.b64 {%0, %1}, %2;" : "=f"(lo), "=f"(hi) : "l"(v));
}
DINL unsigned long long fma2(unsigned long long a, unsigned long long b, unsigned long long c) {
    unsigned long long d;
    asm("fma.rn.f32x2 %0, %1, %2, %3;" : "=l"(d) : "l"(a), "l"(b), "l"(c));
    return d;
}
DINL unsigned long long mul2(unsigned long long a, unsigned long long b) {
    unsigned long long d;
    asm("mul.rn.f32x2 %0, %1, %2;" : "=l"(d) : "l"(a), "l"(b));
    return d;
}
DINL float ex2(float x) {
    float r;
    asm("ex2.approx.f32 %0, %1;" : "=f"(r) : "f"(x));
    return r;
}
DINL uint32_t f2tf32(float v) {
    uint32_t u;
    asm("cvt.rna.tf32.f32 %0, %1;" : "=r"(u) : "f"(v));
    return u;
}

// m16n8k8 tf32 mma: C(f32) += A(tf32) * B(tf32)
#define MMA_TF32(c, a0, a1, a2, a3, b0, b1)                                   \
    asm volatile(                                                             \
        "mma.sync.aligned.m16n8k8.row.col.f32.tf32.tf32.f32 "                 \
        "{%0,%1,%2,%3}, {%4,%5,%6,%7}, {%8,%9}, {%0,%1,%2,%3};"               \
        : "+f"((c)[0]), "+f"((c)[1]), "+f"((c)[2]), "+f"((c)[3])              \
        : "r"(a0), "r"(a1), "r"(a2), "r"(a3), "r"(b0), "r"(b1))

// scratch (no allocation allowed -> __device__ globals)
__device__ float g_delta[16 * 4096 * 8];   // [b][n][8]
__device__ float g_phiP [16 * 8 * 1024];   // [b][c1][1024]
__device__ float g_gP   [16 * 1024 * 32];  // [b][m][32]

// ---------------------------------------------------------------------------
// Kernel 1: fused 3x conv1x1 (48 out ch) + 2x2 maxpool for phi/g. (proven)
// ---------------------------------------------------------------------------
__global__ __launch_bounds__(256, 1) void conv_pool_kernel(
    const float* __restrict__ x,
    const float* __restrict__ w_delta, const float* __restrict__ b_delta,
    const float* __restrict__ w_phi,   const float* __restrict__ b_phi,
    const float* __restrict__ w_g,     const float* __restrict__ b_g)
{
    __shared__ ulonglong2 ws[64][12];
    __shared__ float bias[48];
    const int tid = threadIdx.x;

    for (int i = tid; i < 3072; i += 256) {
        int c = i / 48, o = i - c * 48;
        float w;
        if (o < 8)       w = w_delta[o * 64 + c];
        else if (o < 16) w = w_phi[(o - 8) * 64 + c];
        else             w = w_g[(o - 16) * 64 + c];
        ((float*)&ws[c][0])[o] = w;
    }
    if (tid < 48)
        bias[tid] = (tid < 8) ? b_delta[tid] : (tid < 16) ? b_phi[tid - 8] : b_g[tid - 16];
    __syncthreads();

    const int b   = blockIdx.y;
    const int t   = blockIdx.x * 256 + tid;
    const int q   = t >> 1;
    const int col = t & 1;
    const int qy  = q >> 5, qx = q & 31;
    const int xcol = 2 * qx + col;
    const int row0 = 2 * qy;

    const float* xp = x + (size_t)b * 262144 + row0 * 64 + xcol;

    unsigned long long a0[24], a1[24];
#pragma unroll
    for (int k = 0; k < 24; k++) { a0[k] = 0ull; a1[k] = 0ull; }

#pragma unroll 4
    for (int c = 0; c < 64; c++) {
        float xv0 = xp[c * 4096];
        float xv1 = xp[c * 4096 + 64];
        unsigned long long x0 = pk2(xv0, xv0);
        unsigned long long x1 = pk2(xv1, xv1);
#pragma unroll
        for (int k = 0; k < 12; k++) {
            ulonglong2 w = ws[c][k];
            a0[2*k]   = fma2(w.x, x0, a0[2*k]);
            a0[2*k+1] = fma2(w.y, x0, a0[2*k+1]);
            a1[2*k]   = fma2(w.x, x1, a1[2*k]);
            a1[2*k+1] = fma2(w.y, x1, a1[2*k+1]);
        }
    }

    float f0[48], f1[48];
#pragma unroll
    for (int k = 0; k < 24; k++) {
        upk2(a0[k], f0[2*k], f0[2*k+1]);
        upk2(a1[k], f1[2*k], f1[2*k+1]);
    }

    float* dp0 = g_delta + ((size_t)(b * 4096 + row0 * 64 + xcol)) * 8;
#pragma unroll
    for (int j = 0; j < 8; j++) {
        dp0[j]          = f0[j] + bias[j];
        dp0[64 * 8 + j] = f1[j] + bias[j];
    }

    float pm[40];
#pragma unroll
    for (int j = 0; j < 40; j++) {
        float v = fmaxf(f0[8 + j], f1[8 + j]);
        pm[j] = fmaxf(v, __shfl_xor_sync(0xffffffffu, v, 1));
    }
    float* gp = g_gP + ((size_t)(b * 1024 + q)) * 32;
    if (col == 0) {
#pragma unroll
        for (int j = 0; j < 8; j++)
            g_phiP[(b * 8 + j) * 1024 + q] = pm[j] + bias[8 + j];
#pragma unroll
        for (int j = 0; j < 16; j++)
            gp[j] = pm[8 + j] + bias[16 + j];
    } else {
#pragma unroll
        for (int j = 16; j < 32; j++)
            gp[j] = pm[8 + j] + bias[16 + j];
    }
}

// ---------------------------------------------------------------------------
// Kernel 2: attention (tf32 mma QK + PV, register exp) + fused conv+residual.
// grid (8,16): 512 queries/CTA, 256 threads (8 warps). Warp wid owns query
// m-tiles wid*4..wid*4+3 (rows (wid*4+i)*16 .. +15).
// smem (floats):
//   Vu  : [32 c][1028]  tf32 bits        @ 0      (32896)
//   Kt  : [8 c][1032]   tf32 bits        @ 32896  ( 8256)
//   Pw  : per-warp [16 k][68 q]          @ 41152  ( 8704 = 8*1088)
//   wls : w_last [64][32]                @ 49856  ( 2048)
//   bls : b_last                         @ 51904  (   64)
//   lS  : per-query sum-exp              @ 51968  (  512)
// total 52480 floats = 209920 B. Osm (512x33) reuses Vu region in epilogue.
// ---------------------------------------------------------------------------
static constexpr int SM_FLOATS = 52480;

__global__ __launch_bounds__(256, 1) void attn_kernel(
    const float* __restrict__ x,
    const float* __restrict__ w_last, const float* __restrict__ b_last,
    const float* __restrict__ gamma,  float* __restrict__ out)
{
    extern __shared__ float sm[];
    uint32_t* Vu  = (uint32_t*)sm;              // [32][1028]
    uint32_t* Kt  = (uint32_t*)(sm + 32896);    // [8][1032]
    float*    wls = sm + 49856;
    float*    bls = sm + 51904;
    float*    lS  = sm + 51968;

    const int tid  = threadIdx.x;
    const int wid  = tid >> 5;
    const int lane = tid & 31;
    const int g    = lane >> 2;         // 0..7
    const int t    = lane & 3;          // 0..3
    const int b    = blockIdx.y;

    float* Pw = sm + 41152 + wid * 1088;        // per-warp [16][68]

    // V fill (transposed, tf32): Vu[c*1028 + m] = tf32(g_gP[b][m][c])
    for (int m = tid; m < 1024; m += 256) {
        const float4* gv = (const float4*)(g_gP + ((size_t)(b * 1024 + m)) * 32);
        float4 v4[8];
#pragma unroll
        for (int k = 0; k < 8; k++) v4[k] = gv[k];
        const float* vf = (const float*)v4;
#pragma unroll
        for (int c = 0; c < 32; c++) Vu[c * 1028 + m] = f2tf32(vf[c]);
    }
    // K fill (tf32, batch-mix gather): Kt[c][m]
#pragma unroll
    for (int j = 0; j < 8; j++) {
        int idx = b * 8 + j;
        const float* src = g_phiP + (size_t)((idx & 15) * 8 + (idx >> 4)) * 1024;
        for (int m = tid; m < 1024; m += 256) Kt[j * 1032 + m] = f2tf32(src[m]);
    }
    for (int i = tid; i < 2048; i += 256) wls[i] = w_last[i];
    if (tid < 64) bls[tid] = b_last[tid];
    __syncthreads();

    // Q A-frags (log2e folded, tf32): qf[i] = {A[g][t], A[g+8][t], A[g][t+4], A[g+8][t+4]}
    const float L2E = 1.4426950408889634f;
    const int qbase = blockIdx.x * 512;
    uint32_t qf[4][4];
#pragma unroll
    for (int i = 0; i < 4; i++) {
        const float* d0 = g_delta + ((size_t)b * 4096 + qbase + (wid * 4 + i) * 16 + g) * 8;
        const float* d1 = d0 + 8 * 8;   // +8 rows
        qf[i][0] = f2tf32(L2E * d0[t]);
        qf[i][1] = f2tf32(L2E * d1[t]);
        qf[i][2] = f2tf32(L2E * d0[t + 4]);
        qf[i][3] = f2tf32(L2E * d1[t + 4]);
    }

    float acc[4][16];                   // PV C-frags: [i][nt*4 + j]
    float lp[4][2];                     // l partials: [i][row g / g+8]
#pragma unroll
    for (int i = 0; i < 4; i++) {
#pragma unroll
        for (int k = 0; k < 16; k++) acc[i][k] = 0.f;
        lp[i][0] = 0.f; lp[i][1] = 0.f;
    }

    for (int ci = 0; ci < 64; ci++) {
        const int m0 = ci << 4;

        // K B-frags for the 2 n-tiles of this chunk
        uint32_t kb0[2], kb1[2];
#pragma unroll
        for (int nt = 0; nt < 2; nt++) {
            kb0[nt] = Kt[t * 1032 + m0 + nt * 8 + g];
            kb1[nt] = Kt[(t + 4) * 1032 + m0 + nt * 8 + g];
        }

        __syncwarp();   // prev chunk's P reads complete before overwrite

        // ---- QK mma -> exp (regs) -> stage to per-warp Pw ----
#pragma unroll
        for (int i = 0; i < 4; i++) {
#pragma unroll
            for (int nt = 0; nt < 2; nt++) {
                float c4[4] = {0.f, 0.f, 0.f, 0.f};
                MMA_TF32(c4, qf[i][0], qf[i][1], qf[i][2], qf[i][3], kb0[nt], kb1[nt]);
                float e0 = ex2(c4[0]), e1 = ex2(c4[1]);
                float e2 = ex2(c4[2]), e3 = ex2(c4[3]);
                lp[i][0] += e0 + e1;
                lp[i][1] += e2 + e3;
                // c-frag (row, col): c0=(g,2t) c1=(g,2t+1) c2=(g+8,2t) c3=(g+8,2t+1)
                float* p0 = Pw + (nt * 8 + 2 * t) * 68 + i * 16;
                float* p1 = p0 + 68;
                p0[g]     = e0;
                p1[g]     = e1;
                p0[g + 8] = e2;
                p1[g + 8] = e3;
            }
        }
        __syncwarp();

        // ---- PV mma: A = P (per-warp smem), B = V ----
#pragma unroll
        for (int ks = 0; ks < 2; ks++) {
            const int kb = ks * 8;
            uint32_t bf[4][2];
#pragma unroll
            for (int nt = 0; nt < 4; nt++) {
                bf[nt][0] = Vu[(nt * 8 + g) * 1028 + m0 + kb + t];
                bf[nt][1] = Vu[(nt * 8 + g) * 1028 + m0 + kb + t + 4];
            }
#pragma unroll
            for (int i = 0; i < 4; i++) {
                const float* r0 = Pw + (kb + t) * 68 + i * 16;
                const float* r1 = Pw + (kb + t + 4) * 68 + i * 16;
                uint32_t a0 = __float_as_uint(r0[g]);
                uint32_t a1 = __float_as_uint(r0[g + 8]);
                uint32_t a2 = __float_as_uint(r1[g]);
                uint32_t a3 = __float_as_uint(r1[g + 8]);
                MMA_TF32(acc[i] + 0,  a0, a1, a2, a3, bf[0][0], bf[0][1]);
                MMA_TF32(acc[i] + 4,  a0, a1, a2, a3, bf[1][0], bf[1][1]);
                MMA_TF32(acc[i] + 8,  a0, a1, a2, a3, bf[2][0], bf[2][1]);
                MMA_TF32(acc[i] + 12, a0, a1, a2, a3, bf[3][0], bf[3][1]);
            }
        }
    }

    // ---- l reduction across the 4 t-lanes of each g-group ----
#pragma unroll
    for (int i = 0; i < 4; i++) {
        float l0 = lp[i][0], l1 = lp[i][1];
        l0 += __shfl_xor_sync(0xffffffffu, l0, 1);
        l0 += __shfl_xor_sync(0xffffffffu, l0, 2);
        l1 += __shfl_xor_sync(0xffffffffu, l1, 1);
        l1 += __shfl_xor_sync(0xffffffffu, l1, 2);
        if (t == 0) {
            lS[(wid * 4 + i) * 16 + g]     = l0;
            lS[(wid * 4 + i) * 16 + g + 8] = l1;
        }
    }
    __syncthreads();    // all warps done with Vu before Osm overwrites it

    // ---- scatter O c-frags to smem (over Vu region): Osm[q][33] ----
    float* Osm = sm;
#pragma unroll
    for (int i = 0; i < 4; i++) {
        const int qbse = (wid * 4 + i) * 16;
#pragma unroll
        for (int nt = 0; nt < 4; nt++) {
            const int cb = nt * 8 + 2 * t;
            Osm[(qbse + g)     * 33 + cb]     = acc[i][nt * 4 + 0];
            Osm[(qbse + g)     * 33 + cb + 1] = acc[i][nt * 4 + 1];
            Osm[(qbse + g + 8) * 33 + cb]     = acc[i][nt * 4 + 2];
            Osm[(qbse + g + 8) * 33 + cb + 1] = acc[i][nt * 4 + 3];
        }
    }
    __syncthreads();

    // ---- fused epilogue (proven): 2 queries per thread ----
    const int lq0 = tid, lq1 = tid + 256;
    unsigned long long au0[16], au1[16];
    {
        const float* o0 = Osm + lq0 * 33;
        const float* o1 = Osm + lq1 * 33;
#pragma unroll
        for (int k = 0; k < 16; k++) {
            au0[k] = pk2(o0[2 * k], o0[2 * k + 1]);
            au1[k] = pk2(o1[2 * k], o1[2 * k + 1]);
        }
    }
    const int qg0 = qbase + lq0;
    const int qg1 = qbase + lq1;
    const float gm  = gamma[0];
    const float gi0 = __fdividef(gm, lS[lq0]);
    const float gi1 = __fdividef(gm, lS[lq1]);
    const float* xb = x   + (size_t)b * 262144;
    float*       ob = out + (size_t)b * 262144;
    const ulonglong2* wl2 = (const ulonglong2*)wls;

    for (int c = 0; c < 64; c++) {
        const ulonglong2* wr = wl2 + c * 8;
        ulonglong2 w0 = wr[0];
        unsigned long long s0 = mul2(au0[0], w0.x);
        unsigned long long s1 = mul2(au1[0], w0.x);
        s0 = fma2(au0[1], w0.y, s0);
        s1 = fma2(au1[1], w0.y, s1);
#pragma unroll
        for (int k = 1; k < 8; k++) {
            ulonglong2 w = wr[k];
            s0 = fma2(au0[2*k],   w.x, s0);
            s1 = fma2(au1[2*k],   w.x, s1);
            s0 = fma2(au0[2*k+1], w.y, s0);
            s1 = fma2(au1[2*k+1], w.y, s1);
        }
        float r0a, r0b, r1a, r1b;
        upk2(s0, r0a, r0b);
        upk2(s1, r1a, r1b);
        float base = gm * bls[c];
        ob[c * 4096 + qg0] = fmaf(gi0, r0a + r0b, base + xb[c * 4096 + qg0]);
        ob[c * 4096 + qg1] = fmaf(gi1, r1a + r1b, base + xb[c * 4096 + qg1]);
    }
}

// ---------------------------------------------------------------------------
extern "C" void kernel_launch(void* const* d_in, const int* in_sizes, int n_in,
                              void* d_out, int out_size)
{
    const float* x  = (const float*)d_in[0];
    const float* wd = (const float*)d_in[1];
    const float* bd = (const float*)d_in[2];
    const float* wp = (const float*)d_in[3];
    const float* bp = (const float*)d_in[4];
    const float* wg = (const float*)d_in[5];
    const float* bg = (const float*)d_in[6];
    const float* wl = (const float*)d_in[7];
    const float* bl = (const float*)d_in[8];
    const float* gm = (const float*)d_in[9];

    conv_pool_kernel<<<dim3(8, 16), 256>>>(x, wd, bd, wp, bp, wg, bg);

    const int shm = SM_FLOATS * 4;   // 209920 B
    cudaFuncSetAttribute(attn_kernel, cudaFuncAttributeMaxDynamicSharedMemorySize, shm);
    attn_kernel<<<dim3(8, 16), 256, shm>>>(x, wl, bl, gm, (float*)d_out);
}

// round 15
// speedup vs baseline: 2.3952x; 1.0307x over previous
#include <cuda_runtime.h>
#include <cstdint>
#include <cstddef>

// ---------------------------------------------------------------------------
// NonLocalBlock: B=16, C=64, H=W=64, C1=8, C2=32
// out = gamma * conv1x1(attn_out, w_last, b_last) + x
// Attention v4: tf32 mma QK + PV, register exp, per-warp P staging,
// 512 threads (16 warps, 2 q-tiles/warp) for latency hiding.
// ---------------------------------------------------------------------------

#define DINL __device__ __forceinline__

DINL unsigned long long pk2(float lo, float hi) {
    unsigned long long r;
    asm("mov.b64 %0, {%1, %2};" : "=l"(r) : "f"(lo), "f"(hi));
    return r;
}
DINL void upk2(unsigned long long v, float& lo, float& hi) {
    asm("mov.b64 {%0, %1}, %2;" : "=f"(lo), "=f"(hi) : "l"(v));
}
DINL unsigned long long fma2(unsigned long long a, unsigned long long b, unsigned long long c) {
    unsigned long long d;
    asm("fma.rn.f32x2 %0, %1, %2, %3;" : "=l"(d) : "l"(a), "l"(b), "l"(c));
    return d;
}
DINL unsigned long long mul2(unsigned long long a, unsigned long long b) {
    unsigned long long d;
    asm("mul.rn.f32x2 %0, %1, %2;" : "=l"(d) : "l"(a), "l"(b));
    return d;
}
DINL float ex2(float x) {
    float r;
    asm("ex2.approx.f32 %0, %1;" : "=f"(r) : "f"(x));
    return r;
}
DINL uint32_t f2tf32(float v) {
    uint32_t u;
    asm("cvt.rna.tf32.f32 %0, %1;" : "=r"(u) : "f"(v));
    return u;
}

// m16n8k8 tf32 mma: C(f32) += A(tf32) * B(tf32)
#define MMA_TF32(c, a0, a1, a2, a3, b0, b1)                                   \
    asm volatile(                                                             \
        "mma.sync.aligned.m16n8k8.row.col.f32.tf32.tf32.f32 "                 \
        "{%0,%1,%2,%3}, {%4,%5,%6,%7}, {%8,%9}, {%0,%1,%2,%3};"               \
        : "+f"((c)[0]), "+f"((c)[1]), "+f"((c)[2]), "+f"((c)[3])              \
        : "r"(a0), "r"(a1), "r"(a2), "r"(a3), "r"(b0), "r"(b1))

// scratch (no allocation allowed -> __device__ globals)
__device__ float g_delta[16 * 4096 * 8];   // [b][n][8]
__device__ float g_phiP [16 * 8 * 1024];   // [b][c1][1024]
__device__ float g_gP   [16 * 1024 * 32];  // [b][m][32]

// ---------------------------------------------------------------------------
// Kernel 1: fused 3x conv1x1 (48 out ch) + 2x2 maxpool for phi/g. (proven)
// ---------------------------------------------------------------------------
__global__ __launch_bounds__(256, 1) void conv_pool_kernel(
    const float* __restrict__ x,
    const float* __restrict__ w_delta, const float* __restrict__ b_delta,
    const float* __restrict__ w_phi,   const float* __restrict__ b_phi,
    const float* __restrict__ w_g,     const float* __restrict__ b_g)
{
    __shared__ ulonglong2 ws[64][12];
    __shared__ float bias[48];
    const int tid = threadIdx.x;

    for (int i = tid; i < 3072; i += 256) {
        int c = i / 48, o = i - c * 48;
        float w;
        if (o < 8)       w = w_delta[o * 64 + c];
        else if (o < 16) w = w_phi[(o - 8) * 64 + c];
        else             w = w_g[(o - 16) * 64 + c];
        ((float*)&ws[c][0])[o] = w;
    }
    if (tid < 48)
        bias[tid] = (tid < 8) ? b_delta[tid] : (tid < 16) ? b_phi[tid - 8] : b_g[tid - 16];
    __syncthreads();

    const int b   = blockIdx.y;
    const int t   = blockIdx.x * 256 + tid;
    const int q   = t >> 1;
    const int col = t & 1;
    const int qy  = q >> 5, qx = q & 31;
    const int xcol = 2 * qx + col;
    const int row0 = 2 * qy;

    const float* xp = x + (size_t)b * 262144 + row0 * 64 + xcol;

    unsigned long long a0[24], a1[24];
#pragma unroll
    for (int k = 0; k < 24; k++) { a0[k] = 0ull; a1[k] = 0ull; }

#pragma unroll 4
    for (int c = 0; c < 64; c++) {
        float xv0 = xp[c * 4096];
        float xv1 = xp[c * 4096 + 64];
        unsigned long long x0 = pk2(xv0, xv0);
        unsigned long long x1 = pk2(xv1, xv1);
#pragma unroll
        for (int k = 0; k < 12; k++) {
            ulonglong2 w = ws[c][k];
            a0[2*k]   = fma2(w.x, x0, a0[2*k]);
            a0[2*k+1] = fma2(w.y, x0, a0[2*k+1]);
            a1[2*k]   = fma2(w.x, x1, a1[2*k]);
            a1[2*k+1] = fma2(w.y, x1, a1[2*k+1]);
        }
    }

    float f0[48], f1[48];
#pragma unroll
    for (int k = 0; k < 24; k++) {
        upk2(a0[k], f0[2*k], f0[2*k+1]);
        upk2(a1[k], f1[2*k], f1[2*k+1]);
    }

    float* dp0 = g_delta + ((size_t)(b * 4096 + row0 * 64 + xcol)) * 8;
#pragma unroll
    for (int j = 0; j < 8; j++) {
        dp0[j]          = f0[j] + bias[j];
        dp0[64 * 8 + j] = f1[j] + bias[j];
    }

    float pm[40];
#pragma unroll
    for (int j = 0; j < 40; j++) {
        float v = fmaxf(f0[8 + j], f1[8 + j]);
        pm[j] = fmaxf(v, __shfl_xor_sync(0xffffffffu, v, 1));
    }
    float* gp = g_gP + ((size_t)(b * 1024 + q)) * 32;
    if (col == 0) {
#pragma unroll
        for (int j = 0; j < 8; j++)
            g_phiP[(b * 8 + j) * 1024 + q] = pm[j] + bias[8 + j];
#pragma unroll
        for (int j = 0; j < 16; j++)
            gp[j] = pm[8 + j] + bias[16 + j];
    } else {
#pragma unroll
        for (int j = 16; j < 32; j++)
            gp[j] = pm[8 + j] + bias[16 + j];
    }
}

// ---------------------------------------------------------------------------
// Kernel 2: attention (tf32 mma QK + PV) + fused conv + residual.
// grid (8,16): 512 queries/CTA, 512 threads (16 warps). Warp wid owns query
// m-tiles wid*2, wid*2+1 (rows (wid*2+i)*16 .. +15).
// smem (floats):
//   Vu  : [32 c][1028]  tf32 bits        @ 0      (32896)
//   Kt  : [8 c][1032]   tf32 bits        @ 32896  ( 8256)
//   Pw  : per-warp [16 k][36 q]          @ 41152  ( 9216 = 16*576)
//   wls : w_last [64][32]                @ 50368  ( 2048)
//   bls : b_last                         @ 52416  (   64)
//   lS  : per-query sum-exp              @ 52480  (  512)
// total 52992 floats = 211968 B. Osm (512x33) reuses Vu region in epilogue.
// ---------------------------------------------------------------------------
static constexpr int SM_FLOATS = 52992;

__global__ __launch_bounds__(512, 1) void attn_kernel(
    const float* __restrict__ x,
    const float* __restrict__ w_last, const float* __restrict__ b_last,
    const float* __restrict__ gamma,  float* __restrict__ out)
{
    extern __shared__ float sm[];
    uint32_t* Vu  = (uint32_t*)sm;              // [32][1028]
    uint32_t* Kt  = (uint32_t*)(sm + 32896);    // [8][1032]
    float*    wls = sm + 50368;
    float*    bls = sm + 52416;
    float*    lS  = sm + 52480;

    const int tid  = threadIdx.x;
    const int wid  = tid >> 5;
    const int lane = tid & 31;
    const int g    = lane >> 2;         // 0..7
    const int t    = lane & 3;          // 0..3
    const int b    = blockIdx.y;

    float* Pw = sm + 41152 + wid * 576;         // per-warp [16][36]

    // V fill (transposed, tf32): Vu[c*1028 + m] = tf32(g_gP[b][m][c])
    for (int m = tid; m < 1024; m += 512) {
        const float4* gv = (const float4*)(g_gP + ((size_t)(b * 1024 + m)) * 32);
        float4 v4[8];
#pragma unroll
        for (int k = 0; k < 8; k++) v4[k] = gv[k];
        const float* vf = (const float*)v4;
#pragma unroll
        for (int c = 0; c < 32; c++) Vu[c * 1028 + m] = f2tf32(vf[c]);
    }
    // K fill (tf32, batch-mix gather): Kt[c][m]
#pragma unroll
    for (int j = 0; j < 8; j++) {
        int idx = b * 8 + j;
        const float* src = g_phiP + (size_t)((idx & 15) * 8 + (idx >> 4)) * 1024;
        for (int m = tid; m < 1024; m += 512) Kt[j * 1032 + m] = f2tf32(src[m]);
    }
    for (int i = tid; i < 2048; i += 512) wls[i] = w_last[i];
    if (tid < 64) bls[tid] = b_last[tid];
    __syncthreads();

    // Q A-frags (log2e folded, tf32): qf[i] = {A[g][t], A[g+8][t], A[g][t+4], A[g+8][t+4]}
    const float L2E = 1.4426950408889634f;
    const int qbase = blockIdx.x * 512;
    uint32_t qf[2][4];
#pragma unroll
    for (int i = 0; i < 2; i++) {
        const float* d0 = g_delta + ((size_t)b * 4096 + qbase + (wid * 2 + i) * 16 + g) * 8;
        const float* d1 = d0 + 8 * 8;   // +8 rows
        qf[i][0] = f2tf32(L2E * d0[t]);
        qf[i][1] = f2tf32(L2E * d1[t]);
        qf[i][2] = f2tf32(L2E * d0[t + 4]);
        qf[i][3] = f2tf32(L2E * d1[t + 4]);
    }

    float acc[2][16];                   // PV C-frags: [i][nt*4 + j]
    float lp[2][2];                     // l partials: [i][row g / g+8]
#pragma unroll
    for (int i = 0; i < 2; i++) {
#pragma unroll
        for (int k = 0; k < 16; k++) acc[i][k] = 0.f;
        lp[i][0] = 0.f; lp[i][1] = 0.f;
    }

    for (int ci = 0; ci < 64; ci++) {
        const int m0 = ci << 4;

        // K B-frags for the 2 n-tiles of this chunk
        uint32_t kb0[2], kb1[2];
#pragma unroll
        for (int nt = 0; nt < 2; nt++) {
            kb0[nt] = Kt[t * 1032 + m0 + nt * 8 + g];
            kb1[nt] = Kt[(t + 4) * 1032 + m0 + nt * 8 + g];
        }

        __syncwarp();   // prev chunk's P reads complete before overwrite

        // ---- QK mma -> exp (regs) -> stage to per-warp Pw ----
#pragma unroll
        for (int i = 0; i < 2; i++) {
#pragma unroll
            for (int nt = 0; nt < 2; nt++) {
                float c4[4] = {0.f, 0.f, 0.f, 0.f};
                MMA_TF32(c4, qf[i][0], qf[i][1], qf[i][2], qf[i][3], kb0[nt], kb1[nt]);
                float e0 = ex2(c4[0]), e1 = ex2(c4[1]);
                float e2 = ex2(c4[2]), e3 = ex2(c4[3]);
                lp[i][0] += e0 + e1;
                lp[i][1] += e2 + e3;
                // c-frag (row, col): c0=(g,2t) c1=(g,2t+1) c2=(g+8,2t) c3=(g+8,2t+1)
                float* p0 = Pw + (nt * 8 + 2 * t) * 36 + i * 16;
                float* p1 = p0 + 36;
                p0[g]     = e0;
                p1[g]     = e1;
                p0[g + 8] = e2;
                p1[g + 8] = e3;
            }
        }
        __syncwarp();

        // ---- PV mma: A = P (per-warp smem), B = V ----
#pragma unroll
        for (int ks = 0; ks < 2; ks++) {
            const int kb = ks * 8;
            uint32_t bf[4][2];
#pragma unroll
            for (int nt = 0; nt < 4; nt++) {
                bf[nt][0] = Vu[(nt * 8 + g) * 1028 + m0 + kb + t];
                bf[nt][1] = Vu[(nt * 8 + g) * 1028 + m0 + kb + t + 4];
            }
#pragma unroll
            for (int i = 0; i < 2; i++) {
                const float* r0 = Pw + (kb + t) * 36 + i * 16;
                const float* r1 = Pw + (kb + t + 4) * 36 + i * 16;
                uint32_t a0 = __float_as_uint(r0[g]);
                uint32_t a1 = __float_as_uint(r0[g + 8]);
                uint32_t a2 = __float_as_uint(r1[g]);
                uint32_t a3 = __float_as_uint(r1[g + 8]);
                MMA_TF32(acc[i] + 0,  a0, a1, a2, a3, bf[0][0], bf[0][1]);
                MMA_TF32(acc[i] + 4,  a0, a1, a2, a3, bf[1][0], bf[1][1]);
                MMA_TF32(acc[i] + 8,  a0, a1, a2, a3, bf[2][0], bf[2][1]);
                MMA_TF32(acc[i] + 12, a0, a1, a2, a3, bf[3][0], bf[3][1]);
            }
        }
    }

    // ---- l reduction across the 4 t-lanes of each g-group ----
#pragma unroll
    for (int i = 0; i < 2; i++) {
        float l0 = lp[i][0], l1 = lp[i][1];
        l0 += __shfl_xor_sync(0xffffffffu, l0, 1);
        l0 += __shfl_xor_sync(0xffffffffu, l0, 2);
        l1 += __shfl_xor_sync(0xffffffffu, l1, 1);
        l1 += __shfl_xor_sync(0xffffffffu, l1, 2);
        if (t == 0) {
            lS[(wid * 2 + i) * 16 + g]     = l0;
            lS[(wid * 2 + i) * 16 + g + 8] = l1;
        }
    }
    __syncthreads();    // all warps done with Vu before Osm overwrites it

    // ---- scatter O c-frags to smem (over Vu region): Osm[q][33] ----
    float* Osm = sm;
#pragma unroll
    for (int i = 0; i < 2; i++) {
        const int qbse = (wid * 2 + i) * 16;
#pragma unroll
        for (int nt = 0; nt < 4; nt++) {
            const int cb = nt * 8 + 2 * t;
            Osm[(qbse + g)     * 33 + cb]     = acc[i][nt * 4 + 0];
            Osm[(qbse + g)     * 33 + cb + 1] = acc[i][nt * 4 + 1];
            Osm[(qbse + g + 8) * 33 + cb]     = acc[i][nt * 4 + 2];
            Osm[(qbse + g + 8) * 33 + cb + 1] = acc[i][nt * 4 + 3];
        }
    }
    __syncthreads();

    // ---- fused epilogue (proven math): 1 query per thread ----
    unsigned long long au[16];
    {
        const float* o0 = Osm + tid * 33;
#pragma unroll
        for (int k = 0; k < 16; k++) au[k] = pk2(o0[2 * k], o0[2 * k + 1]);
    }
    const int qg = qbase + tid;
    const float gm = gamma[0];
    const float gi = __fdividef(gm, lS[tid]);
    const float* xb = x   + (size_t)b * 262144;
    float*       ob = out + (size_t)b * 262144;
    const ulonglong2* wl2 = (const ulonglong2*)wls;

    for (int c = 0; c < 64; c++) {
        const ulonglong2* wr = wl2 + c * 8;
        ulonglong2 w0 = wr[0];
        unsigned long long s0 = mul2(au[0], w0.x);
        s0 = fma2(au[1], w0.y, s0);
#pragma unroll
        for (int k = 1; k < 8; k++) {
            ulonglong2 w = wr[k];
            s0 = fma2(au[2*k],   w.x, s0);
            s0 = fma2(au[2*k+1], w.y, s0);
        }
        float ra, rb;
        upk2(s0, ra, rb);
        ob[c * 4096 + qg] = fmaf(gi, ra + rb, fmaf(gm, bls[c], xb[c * 4096 + qg]));
    }
}

// ---------------------------------------------------------------------------
extern "C" void kernel_launch(void* const* d_in, const int* in_sizes, int n_in,
                              void* d_out, int out_size)
{
    const float* x  = (const float*)d_in[0];
    const float* wd = (const float*)d_in[1];
    const float* bd = (const float*)d_in[2];
    const float* wp = (const float*)d_in[3];
    const float* bp = (const float*)d_in[4];
    const float* wg = (const float*)d_in[5];
    const float* bg = (const float*)d_in[6];
    const float* wl = (const float*)d_in[7];
    const float* bl = (const float*)d_in[8];
    const float* gm = (const float*)d_in[9];

    conv_pool_kernel<<<dim3(8, 16), 256>>>(x, wd, bd, wp, bp, wg, bg);

    const int shm = SM_FLOATS * 4;   // 211968 B
    cudaFuncSetAttribute(attn_kernel, cudaFuncAttributeMaxDynamicSharedMemorySize, shm);
    attn_kernel<<<dim3(8, 16), 512, shm>>>(x, wl, bl, gm, (float*)d_out);
}